// round 1
// baseline (speedup 1.0000x reference)
#include <cuda_runtime.h>

#define EMBED 1024
#define HEADS 16
#define DK 64
#define BATCH 2
#define SEQ 2048
#define MTOT (BATCH*SEQ)   // 4096

// Scratch (allocation-free rule: __device__ globals)
__device__ float g_q[(size_t)BATCH*HEADS*SEQ*DK];
__device__ float g_k[(size_t)BATCH*HEADS*SEQ*DK];
__device__ float g_v[(size_t)BATCH*HEADS*SEQ*DK];
__device__ float g_att[(size_t)MTOT*EMBED];

// ---------------------------------------------------------------------------
// Tiled SGEMM: C[M,N] = A[M,K] * W[N,K]^T  (both K-contiguous row-major)
// BM=BN=128, BK=16, 256 threads, 8x8 per thread.
// head_layout=1: scatter into [B,H,S,DK]; head_layout=0: plain [M,N] + bias.
// ---------------------------------------------------------------------------
#define BM 128
#define BN 128
#define BKK 16

__global__ __launch_bounds__(256, 2) void gemm_kernel(
    const float* __restrict__ A, const float* __restrict__ W,
    float* __restrict__ O, const float* __restrict__ bias, int head_layout)
{
    __shared__ float As[BKK][BM];
    __shared__ float Bs[BKK][BN];

    const int m0 = blockIdx.y * BM;
    const int n0 = blockIdx.x * BN;
    const int tid = threadIdx.x;
    const int tx = tid & 15;
    const int ty = tid >> 4;

    const int lrow = tid >> 2;          // 0..63
    const int lk   = (tid & 3) << 2;    // 0,4,8,12

    float c[8][8];
    #pragma unroll
    for (int i = 0; i < 8; i++)
        #pragma unroll
        for (int j = 0; j < 8; j++) c[i][j] = 0.f;

    for (int k0 = 0; k0 < EMBED; k0 += BKK) {
        // stage loads in registers, then sync + store (hides latency)
        float4 a0 = *(const float4*)(A + (size_t)(m0 + lrow) * EMBED + k0 + lk);
        float4 a1 = *(const float4*)(A + (size_t)(m0 + lrow + 64) * EMBED + k0 + lk);
        float4 w0 = *(const float4*)(W + (size_t)(n0 + lrow) * EMBED + k0 + lk);
        float4 w1 = *(const float4*)(W + (size_t)(n0 + lrow + 64) * EMBED + k0 + lk);

        __syncthreads();
        As[lk+0][lrow] = a0.x; As[lk+1][lrow] = a0.y; As[lk+2][lrow] = a0.z; As[lk+3][lrow] = a0.w;
        As[lk+0][lrow+64] = a1.x; As[lk+1][lrow+64] = a1.y; As[lk+2][lrow+64] = a1.z; As[lk+3][lrow+64] = a1.w;
        Bs[lk+0][lrow] = w0.x; Bs[lk+1][lrow] = w0.y; Bs[lk+2][lrow] = w0.z; Bs[lk+3][lrow] = w0.w;
        Bs[lk+0][lrow+64] = w1.x; Bs[lk+1][lrow+64] = w1.y; Bs[lk+2][lrow+64] = w1.z; Bs[lk+3][lrow+64] = w1.w;
        __syncthreads();

        #pragma unroll
        for (int k = 0; k < BKK; k++) {
            float av[8], bv[8];
            *(float4*)&av[0] = *(const float4*)&As[k][ty * 8];
            *(float4*)&av[4] = *(const float4*)&As[k][ty * 8 + 4];
            *(float4*)&bv[0] = *(const float4*)&Bs[k][tx * 8];
            *(float4*)&bv[4] = *(const float4*)&Bs[k][tx * 8 + 4];
            #pragma unroll
            for (int i = 0; i < 8; i++)
                #pragma unroll
                for (int j = 0; j < 8; j++)
                    c[i][j] = fmaf(av[i], bv[j], c[i][j]);
        }
    }

    if (head_layout) {
        #pragma unroll
        for (int i = 0; i < 8; i++) {
            int m = m0 + ty * 8 + i;
            int b = m >> 11;            // / SEQ
            int s = m & (SEQ - 1);
            #pragma unroll
            for (int jj = 0; jj < 8; jj += 4) {
                int n = n0 + tx * 8 + jj;
                int h = n >> 6;
                int d = n & 63;
                float4 v4 = make_float4(c[i][jj], c[i][jj+1], c[i][jj+2], c[i][jj+3]);
                *(float4*)(O + (((size_t)(b * HEADS + h) * SEQ + s) * DK + d)) = v4;
            }
        }
    } else {
        #pragma unroll
        for (int i = 0; i < 8; i++) {
            int m = m0 + ty * 8 + i;
            #pragma unroll
            for (int jj = 0; jj < 8; jj += 4) {
                int n = n0 + tx * 8 + jj;
                float4 bb = *(const float4*)(bias + n);
                float4 v4 = make_float4(c[i][jj] + bb.x, c[i][jj+1] + bb.y,
                                        c[i][jj+2] + bb.z, c[i][jj+3] + bb.w);
                *(float4*)(O + (size_t)m * EMBED + n) = v4;
            }
        }
    }
}

// ---------------------------------------------------------------------------
// Flash attention, fp32. Block = one (b,h,qtile of 64 rows). 256 threads.
// Thread (ty,tx) owns a 4x4 sub-tile: rows 4ty.., cols/d 4tx..
// Smem (dynamic): Qt[64][68] (k-major), Kt/Ps[64][68] (shared buffer), Vs[64][68].
// ---------------------------------------------------------------------------
#define PADW 68

__global__ __launch_bounds__(256) void attn_kernel()
{
    extern __shared__ float sm[];
    float* Qt   = sm;                  // Qt[k][row]
    float* KtPs = sm + 64 * PADW;      // Kt[k][col], later Ps[row][kk]
    float* Vs   = sm + 2 * 64 * PADW;  // Vs[kk][d]

    const int qt = blockIdx.x;
    const int bh = blockIdx.y;
    const int b = bh >> 4;
    const int h = bh & 15;
    const int tid = threadIdx.x;
    const int tx = tid & 15;
    const int ty = tid >> 4;

    const float* Qg = g_q + ((size_t)bh * SEQ + qt * 64) * DK;
    const float* Kg = g_k + (size_t)bh * SEQ * DK;
    const float* Vg = g_v + (size_t)bh * SEQ * DK;

    // Load Q tile transposed: Qt[d][row]
    #pragma unroll
    for (int it = 0; it < 4; it++) {
        int f = tid + it * 256;
        int r = f >> 4;
        int d4 = (f & 15) << 2;
        float4 v4 = *(const float4*)(Qg + (size_t)r * DK + d4);
        Qt[(d4 + 0) * PADW + r] = v4.x;
        Qt[(d4 + 1) * PADW + r] = v4.y;
        Qt[(d4 + 2) * PADW + r] = v4.z;
        Qt[(d4 + 3) * PADW + r] = v4.w;
    }

    float m_i[4], l_i[4], o[4][4];
    #pragma unroll
    for (int i = 0; i < 4; i++) {
        m_i[i] = -1e30f; l_i[i] = 0.f;
        #pragma unroll
        for (int j = 0; j < 4; j++) o[i][j] = 0.f;
    }

    for (int kt = 0; kt <= qt; kt++) {
        __syncthreads();   // prev PV / Q-store done before overwriting tiles
        // Load K transposed (Kt[d][col]) and V natural (Vs[kk][d])
        #pragma unroll
        for (int it = 0; it < 4; it++) {
            int f = tid + it * 256;
            int r = f >> 4;
            int d4 = (f & 15) << 2;
            float4 k4 = *(const float4*)(Kg + (size_t)(kt * 64 + r) * DK + d4);
            KtPs[(d4 + 0) * PADW + r] = k4.x;
            KtPs[(d4 + 1) * PADW + r] = k4.y;
            KtPs[(d4 + 2) * PADW + r] = k4.z;
            KtPs[(d4 + 3) * PADW + r] = k4.w;
            float4 v4 = *(const float4*)(Vg + (size_t)(kt * 64 + r) * DK + d4);
            *(float4*)&Vs[r * PADW + d4] = v4;
        }
        __syncthreads();

        // S = Q K^T (64x64x64), each thread 4x4
        float s[4][4];
        #pragma unroll
        for (int i = 0; i < 4; i++)
            #pragma unroll
            for (int j = 0; j < 4; j++) s[i][j] = 0.f;

        #pragma unroll 8
        for (int k = 0; k < DK; k++) {
            float4 a  = *(const float4*)&Qt[k * PADW + ty * 4];
            float4 bb = *(const float4*)&KtPs[k * PADW + tx * 4];
            float av[4] = {a.x, a.y, a.z, a.w};
            float bv[4] = {bb.x, bb.y, bb.z, bb.w};
            #pragma unroll
            for (int i = 0; i < 4; i++)
                #pragma unroll
                for (int j = 0; j < 4; j++)
                    s[i][j] = fmaf(av[i], bv[j], s[i][j]);
        }

        const float sc = 0.125f;   // 1/sqrt(64)
        const bool diag = (kt == qt);
        float p[4][4];
        #pragma unroll
        for (int i = 0; i < 4; i++) {
            int ig = ty * 4 + i;
            float mx = -1e30f;
            #pragma unroll
            for (int j = 0; j < 4; j++) {
                float sv = s[i][j] * sc;
                if (diag && (tx * 4 + j) > ig) sv = -1e30f;
                s[i][j] = sv;
                mx = fmaxf(mx, sv);
            }
            #pragma unroll
            for (int msk = 1; msk < 16; msk <<= 1)
                mx = fmaxf(mx, __shfl_xor_sync(0xffffffffu, mx, msk));
            float nm = fmaxf(m_i[i], mx);
            float alpha = __expf(m_i[i] - nm);
            m_i[i] = nm;
            float rs = 0.f;
            #pragma unroll
            for (int j = 0; j < 4; j++) {
                p[i][j] = __expf(s[i][j] - nm);
                rs += p[i][j];
            }
            #pragma unroll
            for (int msk = 1; msk < 16; msk <<= 1)
                rs += __shfl_xor_sync(0xffffffffu, rs, msk);
            l_i[i] = l_i[i] * alpha + rs;
            #pragma unroll
            for (int j = 0; j < 4; j++) o[i][j] *= alpha;
        }

        __syncthreads();   // everyone done reading Kt before overlay with Ps
        #pragma unroll
        for (int i = 0; i < 4; i++)
            *(float4*)&KtPs[(ty * 4 + i) * PADW + tx * 4] =
                make_float4(p[i][0], p[i][1], p[i][2], p[i][3]);
        __syncthreads();

        // O += P V
        #pragma unroll 4
        for (int kk = 0; kk < 64; kk += 4) {
            float pr[4][4];
            #pragma unroll
            for (int i = 0; i < 4; i++)
                *(float4*)&pr[i][0] = *(const float4*)&KtPs[(ty * 4 + i) * PADW + kk];
            #pragma unroll
            for (int cc = 0; cc < 4; cc++) {
                float4 vv = *(const float4*)&Vs[(kk + cc) * PADW + tx * 4];
                #pragma unroll
                for (int i = 0; i < 4; i++) {
                    o[i][0] = fmaf(pr[i][cc], vv.x, o[i][0]);
                    o[i][1] = fmaf(pr[i][cc], vv.y, o[i][1]);
                    o[i][2] = fmaf(pr[i][cc], vv.z, o[i][2]);
                    o[i][3] = fmaf(pr[i][cc], vv.w, o[i][3]);
                }
            }
        }
    }

    // Normalize and write concat-head layout [B,S,E]
    #pragma unroll
    for (int i = 0; i < 4; i++) {
        float inv = 1.0f / l_i[i];
        int rg = qt * 64 + ty * 4 + i;
        float4 out4 = make_float4(o[i][0] * inv, o[i][1] * inv,
                                  o[i][2] * inv, o[i][3] * inv);
        *(float4*)(g_att + (size_t)(b * SEQ + rg) * EMBED + h * DK + tx * 4) = out4;
    }
}

// ---------------------------------------------------------------------------
extern "C" void kernel_launch(void* const* d_in, const int* in_sizes, int n_in,
                              void* d_out, int out_size)
{
    const float* key_   = (const float*)d_in[0];
    const float* query_ = (const float*)d_in[1];
    const float* value_ = (const float*)d_in[2];
    const float* Wq = (const float*)d_in[3];
    const float* Wk = (const float*)d_in[4];
    const float* Wv = (const float*)d_in[5];
    const float* Wo = (const float*)d_in[6];
    const float* bo = (const float*)d_in[7];
    float* out = (float*)d_out;

    float *q_p, *k_p, *v_p, *att_p;
    cudaGetSymbolAddress((void**)&q_p, g_q);
    cudaGetSymbolAddress((void**)&k_p, g_k);
    cudaGetSymbolAddress((void**)&v_p, g_v);
    cudaGetSymbolAddress((void**)&att_p, g_att);

    dim3 blk(256);
    dim3 grid(EMBED / BN, MTOT / BM);

    gemm_kernel<<<grid, blk>>>(query_, Wq, q_p, nullptr, 1);
    gemm_kernel<<<grid, blk>>>(key_,   Wk, k_p, nullptr, 1);
    gemm_kernel<<<grid, blk>>>(value_, Wv, v_p, nullptr, 1);

    int smem = 3 * 64 * PADW * (int)sizeof(float);
    cudaFuncSetAttribute(attn_kernel, cudaFuncAttributeMaxDynamicSharedMemorySize, smem);
    attn_kernel<<<dim3(SEQ / 64, BATCH * HEADS), blk, smem>>>();

    gemm_kernel<<<grid, blk>>>(att_p, Wo, out, bo, 0);
}

// round 3
// speedup vs baseline: 1.6275x; 1.6275x over previous
#include <cuda_runtime.h>
#include <cstdint>

#define EMBED 1024
#define HEADS 16
#define DK 64
#define BATCH 2
#define SEQ 2048
#define MTOT (BATCH*SEQ)   // 4096

// ---------------------------------------------------------------------------
// Scratch (__device__ globals; no allocation allowed)
// ---------------------------------------------------------------------------
__device__ float g_q[(size_t)BATCH*HEADS*SEQ*DK];
__device__ float g_k[(size_t)BATCH*HEADS*SEQ*DK];
__device__ float g_v[(size_t)BATCH*HEADS*SEQ*DK];
__device__ float g_att[(size_t)MTOT*EMBED];
// tf32-rounded weights
__device__ float g_wq[(size_t)EMBED*EMBED];
__device__ float g_wk[(size_t)EMBED*EMBED];
__device__ float g_wv[(size_t)EMBED*EMBED];
__device__ float g_wo[(size_t)EMBED*EMBED];

// ---------------------------------------------------------------------------
// Helpers
// ---------------------------------------------------------------------------
__device__ __forceinline__ uint32_t smem_to_u32(const void* p) {
    uint32_t a;
    asm("{ .reg .u64 t; cvta.to.shared.u64 t, %1; cvt.u32.u64 %0, t; }"
        : "=r"(a) : "l"(p));
    return a;
}
__device__ __forceinline__ uint32_t f2tf32(float x) {
    uint32_t u;
    asm("cvt.rna.tf32.f32 %0, %1;" : "=r"(u) : "f"(x));
    return u;
}
__device__ __forceinline__ void mma_tf32_16x8x8(float c[4], const uint32_t a[4],
                                                const uint32_t b[2]) {
    asm("mma.sync.aligned.m16n8k8.row.col.f32.tf32.tf32.f32 "
        "{%0,%1,%2,%3}, {%4,%5,%6,%7}, {%8,%9}, {%0,%1,%2,%3};"
        : "+f"(c[0]), "+f"(c[1]), "+f"(c[2]), "+f"(c[3])
        : "r"(a[0]), "r"(a[1]), "r"(a[2]), "r"(a[3]), "r"(b[0]), "r"(b[1]));
}
__device__ __forceinline__ void cp16(uint32_t dst, const void* src) {
    asm volatile("cp.async.cg.shared.global [%0], [%1], 16;" :: "r"(dst), "l"(src));
}
#define CP_COMMIT() asm volatile("cp.async.commit_group;" ::: "memory")
#define CP_WAIT1()  asm volatile("cp.async.wait_group 1;" ::: "memory")
#define CP_WAIT0()  asm volatile("cp.async.wait_group 0;" ::: "memory")

// ---------------------------------------------------------------------------
// Elementwise fp32 -> tf32 (rna) pre-pass (weights only)
// ---------------------------------------------------------------------------
__global__ void cvt_tf32_kernel(const float* __restrict__ in, float* __restrict__ out) {
    size_t i = ((size_t)blockIdx.x * 256 + threadIdx.x) * 4;
    float4 v = *(const float4*)(in + i);
    *(uint4*)(out + i) = make_uint4(f2tf32(v.x), f2tf32(v.y), f2tf32(v.z), f2tf32(v.w));
}

// ---------------------------------------------------------------------------
// tf32 mma.sync GEMM: C[M=4096, Ntot=1024] = A[M,1024] * W[Ntot,1024]^T
// CTA 128x128, BK=32, 256 threads (8 warps, 4x2), warp tile 32x64.
// RA=true: round A fragments to tf32 in-register (A not pre-rounded).
// head_layout=1: scatter into [B,H,S,DK]; else plain [M,1024] + bias.
// ---------------------------------------------------------------------------
#define BM 128
#define BN 128
#define BK 32
#define LDT 36                      // smem pitch (floats)
#define TILE_F (BM * LDT)           // 4608 floats per tile
#define GCHUNKS (EMBED / BK)        // 32

__device__ __forceinline__ void load_chunk(const float* __restrict__ A,
                                           const float* __restrict__ W,
                                           int m0, int n0, int c,
                                           uint32_t sa, uint32_t sb, int tid) {
    const float* Ab = A + (size_t)m0 * EMBED + c * BK;
    #pragma unroll
    for (int it = 0; it < 4; it++) {            // 128 rows * 8 segs of 16B
        int seg = tid + it * 256;
        int r = seg >> 3, s8 = seg & 7;
        cp16(sa + r * (LDT * 4) + s8 * 16, Ab + (size_t)r * EMBED + s8 * 4);
    }
    const float* Wb = W + (size_t)n0 * EMBED + c * BK;
    #pragma unroll
    for (int it = 0; it < 4; it++) {
        int seg = tid + it * 256;
        int r = seg >> 3, s8 = seg & 7;
        cp16(sb + r * (LDT * 4) + s8 * 16, Wb + (size_t)r * EMBED + s8 * 4);
    }
    CP_COMMIT();
}

template <bool RA>
__global__ __launch_bounds__(256, 2) void tc_gemm(
    const float* __restrict__ A, const float* __restrict__ W,
    float* __restrict__ O, const float* __restrict__ bias, int head_layout)
{
    extern __shared__ __align__(16) float sm[];
    float* As[2] = { sm,             sm + 2 * TILE_F };
    float* Bs[2] = { sm + TILE_F,    sm + 3 * TILE_F };
    const uint32_t sa_u[2] = { smem_to_u32(As[0]), smem_to_u32(As[1]) };
    const uint32_t sb_u[2] = { smem_to_u32(Bs[0]), smem_to_u32(Bs[1]) };

    const int tid = threadIdx.x;
    const int lane = tid & 31;
    const int warp = tid >> 5;
    const int wm = warp >> 1;        // 0..3 -> 32-row slice
    const int wn = warp & 1;         // 0..1 -> 64-col slice
    const int qrow = lane >> 2;      // 0..7
    const int qcol = lane & 3;       // 0..3
    const int m0 = blockIdx.y * BM;
    const int n0 = blockIdx.x * BN;

    float c[2][8][4];
    #pragma unroll
    for (int mt = 0; mt < 2; mt++)
        #pragma unroll
        for (int nt = 0; nt < 8; nt++)
            #pragma unroll
            for (int r = 0; r < 4; r++) c[mt][nt][r] = 0.f;

    load_chunk(A, W, m0, n0, 0, sa_u[0], sb_u[0], tid);
    load_chunk(A, W, m0, n0, 1, sa_u[1], sb_u[1], tid);

    for (int ch = 0; ch < GCHUNKS; ch++) {
        const int buf = ch & 1;
        CP_WAIT1();
        __syncthreads();

        const float* Ab = As[buf] + (wm * 32 + qrow) * LDT + qcol;
        const float* Bb = Bs[buf] + (wn * 64 + qrow) * LDT + qcol;

        #pragma unroll
        for (int kk = 0; kk < BK; kk += 8) {
            uint32_t af[2][4];
            #pragma unroll
            for (int mt = 0; mt < 2; mt++) {
                const float* p = Ab + mt * 16 * LDT + kk;
                float x0 = p[0], x1 = p[8 * LDT], x2 = p[4], x3 = p[8 * LDT + 4];
                if (RA) {
                    af[mt][0] = f2tf32(x0); af[mt][1] = f2tf32(x1);
                    af[mt][2] = f2tf32(x2); af[mt][3] = f2tf32(x3);
                } else {
                    af[mt][0] = __float_as_uint(x0); af[mt][1] = __float_as_uint(x1);
                    af[mt][2] = __float_as_uint(x2); af[mt][3] = __float_as_uint(x3);
                }
            }
            uint32_t bf[8][2];
            #pragma unroll
            for (int nt = 0; nt < 8; nt++) {
                const float* p = Bb + nt * 8 * LDT + kk;
                bf[nt][0] = __float_as_uint(p[0]);
                bf[nt][1] = __float_as_uint(p[4]);
            }
            #pragma unroll
            for (int mt = 0; mt < 2; mt++)
                #pragma unroll
                for (int nt = 0; nt < 8; nt++)
                    mma_tf32_16x8x8(c[mt][nt], af[mt], bf[nt]);
        }

        __syncthreads();
        if (ch + 2 < GCHUNKS)
            load_chunk(A, W, m0, n0, ch + 2, sa_u[buf], sb_u[buf], tid);
    }
    CP_WAIT0();

    // Epilogue: direct STG of float2 pairs
    #pragma unroll
    for (int mt = 0; mt < 2; mt++) {
        #pragma unroll
        for (int half = 0; half < 2; half++) {
            const int m = m0 + wm * 32 + mt * 16 + half * 8 + qrow;
            #pragma unroll
            for (int nt = 0; nt < 8; nt++) {
                const int n = n0 + wn * 64 + nt * 8 + 2 * qcol;
                float v0 = c[mt][nt][half * 2 + 0];
                float v1 = c[mt][nt][half * 2 + 1];
                if (head_layout) {
                    const int b = m >> 11, s = m & (SEQ - 1);
                    const int h = n >> 6, dd = n & 63;
                    *(float2*)(O + (((size_t)(b * HEADS + h) * SEQ + s) * DK + dd)) =
                        make_float2(v0, v1);
                } else {
                    float2 bb = *(const float2*)(bias + n);
                    *(float2*)(O + (size_t)m * EMBED + n) =
                        make_float2(v0 + bb.x, v1 + bb.y);
                }
            }
        }
    }
}

// ---------------------------------------------------------------------------
// Flash attention, fp32 SIMT (validated in round 1; epilogue rounds to tf32
// so the O-projection GEMM needs no in-register rounding of A)
// ---------------------------------------------------------------------------
#define PADW 68

__global__ __launch_bounds__(256) void attn_kernel()
{
    extern __shared__ float sm[];
    float* Qt   = sm;
    float* KtPs = sm + 64 * PADW;
    float* Vs   = sm + 2 * 64 * PADW;

    const int qt = blockIdx.x;
    const int bh = blockIdx.y;
    const int b = bh >> 4;
    const int h = bh & 15;
    const int tid = threadIdx.x;
    const int tx = tid & 15;
    const int ty = tid >> 4;

    const float* Qg = g_q + ((size_t)bh * SEQ + qt * 64) * DK;
    const float* Kg = g_k + (size_t)bh * SEQ * DK;
    const float* Vg = g_v + (size_t)bh * SEQ * DK;

    #pragma unroll
    for (int it = 0; it < 4; it++) {
        int f = tid + it * 256;
        int r = f >> 4;
        int d4 = (f & 15) << 2;
        float4 v4 = *(const float4*)(Qg + (size_t)r * DK + d4);
        Qt[(d4 + 0) * PADW + r] = v4.x;
        Qt[(d4 + 1) * PADW + r] = v4.y;
        Qt[(d4 + 2) * PADW + r] = v4.z;
        Qt[(d4 + 3) * PADW + r] = v4.w;
    }

    float m_i[4], l_i[4], o[4][4];
    #pragma unroll
    for (int i = 0; i < 4; i++) {
        m_i[i] = -1e30f; l_i[i] = 0.f;
        #pragma unroll
        for (int j = 0; j < 4; j++) o[i][j] = 0.f;
    }

    for (int kt = 0; kt <= qt; kt++) {
        __syncthreads();
        #pragma unroll
        for (int it = 0; it < 4; it++) {
            int f = tid + it * 256;
            int r = f >> 4;
            int d4 = (f & 15) << 2;
            float4 k4 = *(const float4*)(Kg + (size_t)(kt * 64 + r) * DK + d4);
            KtPs[(d4 + 0) * PADW + r] = k4.x;
            KtPs[(d4 + 1) * PADW + r] = k4.y;
            KtPs[(d4 + 2) * PADW + r] = k4.z;
            KtPs[(d4 + 3) * PADW + r] = k4.w;
            float4 v4 = *(const float4*)(Vg + (size_t)(kt * 64 + r) * DK + d4);
            *(float4*)&Vs[r * PADW + d4] = v4;
        }
        __syncthreads();

        float s[4][4];
        #pragma unroll
        for (int i = 0; i < 4; i++)
            #pragma unroll
            for (int j = 0; j < 4; j++) s[i][j] = 0.f;

        #pragma unroll 8
        for (int k = 0; k < DK; k++) {
            float4 a  = *(const float4*)&Qt[k * PADW + ty * 4];
            float4 bb = *(const float4*)&KtPs[k * PADW + tx * 4];
            float av[4] = {a.x, a.y, a.z, a.w};
            float bv[4] = {bb.x, bb.y, bb.z, bb.w};
            #pragma unroll
            for (int i = 0; i < 4; i++)
                #pragma unroll
                for (int j = 0; j < 4; j++)
                    s[i][j] = fmaf(av[i], bv[j], s[i][j]);
        }

        const float sc = 0.125f;
        const bool diag = (kt == qt);
        float p[4][4];
        #pragma unroll
        for (int i = 0; i < 4; i++) {
            int ig = ty * 4 + i;
            float mx = -1e30f;
            #pragma unroll
            for (int j = 0; j < 4; j++) {
                float sv = s[i][j] * sc;
                if (diag && (tx * 4 + j) > ig) sv = -1e30f;
                s[i][j] = sv;
                mx = fmaxf(mx, sv);
            }
            #pragma unroll
            for (int msk = 1; msk < 16; msk <<= 1)
                mx = fmaxf(mx, __shfl_xor_sync(0xffffffffu, mx, msk));
            float nm = fmaxf(m_i[i], mx);
            float alpha = __expf(m_i[i] - nm);
            m_i[i] = nm;
            float rs = 0.f;
            #pragma unroll
            for (int j = 0; j < 4; j++) {
                p[i][j] = __expf(s[i][j] - nm);
                rs += p[i][j];
            }
            #pragma unroll
            for (int msk = 1; msk < 16; msk <<= 1)
                rs += __shfl_xor_sync(0xffffffffu, rs, msk);
            l_i[i] = l_i[i] * alpha + rs;
            #pragma unroll
            for (int j = 0; j < 4; j++) o[i][j] *= alpha;
        }

        __syncthreads();
        #pragma unroll
        for (int i = 0; i < 4; i++)
            *(float4*)&KtPs[(ty * 4 + i) * PADW + tx * 4] =
                make_float4(p[i][0], p[i][1], p[i][2], p[i][3]);
        __syncthreads();

        #pragma unroll 4
        for (int kk = 0; kk < 64; kk += 4) {
            float pr[4][4];
            #pragma unroll
            for (int i = 0; i < 4; i++)
                *(float4*)&pr[i][0] = *(const float4*)&KtPs[(ty * 4 + i) * PADW + kk];
            #pragma unroll
            for (int cc = 0; cc < 4; cc++) {
                float4 vv = *(const float4*)&Vs[(kk + cc) * PADW + tx * 4];
                #pragma unroll
                for (int i = 0; i < 4; i++) {
                    o[i][0] = fmaf(pr[i][cc], vv.x, o[i][0]);
                    o[i][1] = fmaf(pr[i][cc], vv.y, o[i][1]);
                    o[i][2] = fmaf(pr[i][cc], vv.z, o[i][2]);
                    o[i][3] = fmaf(pr[i][cc], vv.w, o[i][3]);
                }
            }
        }
    }

    // Normalize, round to tf32 (O-projection operand), write [B,S,E]
    #pragma unroll
    for (int i = 0; i < 4; i++) {
        float inv = 1.0f / l_i[i];
        int rg = qt * 64 + ty * 4 + i;
        *(uint4*)(g_att + (size_t)(b * SEQ + rg) * EMBED + h * DK + tx * 4) =
            make_uint4(f2tf32(o[i][0] * inv), f2tf32(o[i][1] * inv),
                       f2tf32(o[i][2] * inv), f2tf32(o[i][3] * inv));
    }
}

// ---------------------------------------------------------------------------
extern "C" void kernel_launch(void* const* d_in, const int* in_sizes, int n_in,
                              void* d_out, int out_size)
{
    const float* key_   = (const float*)d_in[0];
    const float* query_ = (const float*)d_in[1];
    const float* value_ = (const float*)d_in[2];
    const float* Wq = (const float*)d_in[3];
    const float* Wk = (const float*)d_in[4];
    const float* Wv = (const float*)d_in[5];
    const float* Wo = (const float*)d_in[6];
    const float* bo = (const float*)d_in[7];
    float* out = (float*)d_out;

    float *q_p, *k_p, *v_p, *att_p, *wq_p, *wk_p, *wv_p, *wo_p;
    cudaGetSymbolAddress((void**)&q_p,  g_q);
    cudaGetSymbolAddress((void**)&k_p,  g_k);
    cudaGetSymbolAddress((void**)&v_p,  g_v);
    cudaGetSymbolAddress((void**)&att_p, g_att);
    cudaGetSymbolAddress((void**)&wq_p, g_wq);
    cudaGetSymbolAddress((void**)&wk_p, g_wk);
    cudaGetSymbolAddress((void**)&wv_p, g_wv);
    cudaGetSymbolAddress((void**)&wo_p, g_wo);

    // Pre-round weights to tf32 (rna)
    cvt_tf32_kernel<<<EMBED * EMBED / 1024, 256>>>(Wq, wq_p);
    cvt_tf32_kernel<<<EMBED * EMBED / 1024, 256>>>(Wk, wk_p);
    cvt_tf32_kernel<<<EMBED * EMBED / 1024, 256>>>(Wv, wv_p);
    cvt_tf32_kernel<<<EMBED * EMBED / 1024, 256>>>(Wo, wo_p);

    const int gemm_smem = 4 * TILE_F * (int)sizeof(float);   // 73728
    cudaFuncSetAttribute(tc_gemm<true>,  cudaFuncAttributeMaxDynamicSharedMemorySize, gemm_smem);
    cudaFuncSetAttribute(tc_gemm<false>, cudaFuncAttributeMaxDynamicSharedMemorySize, gemm_smem);
    dim3 gg(EMBED / BN, MTOT / BM);   // (8, 32)

    tc_gemm<true><<<gg, 256, gemm_smem>>>(query_, wq_p, q_p, nullptr, 1);
    tc_gemm<true><<<gg, 256, gemm_smem>>>(key_,   wk_p, k_p, nullptr, 1);
    tc_gemm<true><<<gg, 256, gemm_smem>>>(value_, wv_p, v_p, nullptr, 1);

    int smem = 3 * 64 * PADW * (int)sizeof(float);
    cudaFuncSetAttribute(attn_kernel, cudaFuncAttributeMaxDynamicSharedMemorySize, smem);
    attn_kernel<<<dim3(SEQ / 64, BATCH * HEADS), 256, smem>>>();

    tc_gemm<false><<<gg, 256, gemm_smem>>>(att_p, wo_p, out, bo, 0);
}

// round 4
// speedup vs baseline: 2.8834x; 1.7717x over previous
#include <cuda_runtime.h>
#include <cstdint>

#define EMBED 1024
#define HEADS 16
#define DK 64
#define BATCH 2
#define SEQ 2048
#define MTOT (BATCH*SEQ)   // 4096

// ---------------------------------------------------------------------------
// Scratch
// ---------------------------------------------------------------------------
__device__ float g_q[(size_t)BATCH*HEADS*SEQ*DK];
__device__ float g_k[(size_t)BATCH*HEADS*SEQ*DK];
__device__ float g_v[(size_t)BATCH*HEADS*SEQ*DK];
__device__ float g_att[(size_t)MTOT*EMBED];
__device__ float g_wq[(size_t)EMBED*EMBED];
__device__ float g_wk[(size_t)EMBED*EMBED];
__device__ float g_wv[(size_t)EMBED*EMBED];
__device__ float g_wo[(size_t)EMBED*EMBED];

// ---------------------------------------------------------------------------
// Helpers
// ---------------------------------------------------------------------------
__device__ __forceinline__ uint32_t smem_to_u32(const void* p) {
    uint32_t a;
    asm("{ .reg .u64 t; cvta.to.shared.u64 t, %1; cvt.u32.u64 %0, t; }"
        : "=r"(a) : "l"(p));
    return a;
}
__device__ __forceinline__ uint32_t f2tf32(float x) {
    uint32_t u;
    asm("cvt.rna.tf32.f32 %0, %1;" : "=r"(u) : "f"(x));
    return u;
}
__device__ __forceinline__ void mma_tf32_16x8x8(float c[4], const uint32_t a[4],
                                                const uint32_t b[2]) {
    asm("mma.sync.aligned.m16n8k8.row.col.f32.tf32.tf32.f32 "
        "{%0,%1,%2,%3}, {%4,%5,%6,%7}, {%8,%9}, {%0,%1,%2,%3};"
        : "+f"(c[0]), "+f"(c[1]), "+f"(c[2]), "+f"(c[3])
        : "r"(a[0]), "r"(a[1]), "r"(a[2]), "r"(a[3]), "r"(b[0]), "r"(b[1]));
}
__device__ __forceinline__ void cp16(uint32_t dst, const void* src) {
    asm volatile("cp.async.cg.shared.global [%0], [%1], 16;" :: "r"(dst), "l"(src));
}
#define CP_COMMIT() asm volatile("cp.async.commit_group;" ::: "memory")
#define CP_WAIT1()  asm volatile("cp.async.wait_group 1;" ::: "memory")
#define CP_WAIT0()  asm volatile("cp.async.wait_group 0;" ::: "memory")

// within-8 k-axis permutation: pairs (b, b+4) become adjacent slots
__device__ __host__ __forceinline__ int sig8(int b) { return ((b & 3) << 1) | (b >> 2); }

// ---------------------------------------------------------------------------
// fp32 -> tf32 (rna) pre-pass for weights
// ---------------------------------------------------------------------------
__global__ void cvt_tf32_kernel(const float* __restrict__ in, float* __restrict__ out) {
    size_t i = ((size_t)blockIdx.x * 256 + threadIdx.x) * 4;
    float4 v = *(const float4*)(in + i);
    *(uint4*)(out + i) = make_uint4(f2tf32(v.x), f2tf32(v.y), f2tf32(v.z), f2tf32(v.w));
}

// ---------------------------------------------------------------------------
// tf32 mma.sync GEMM: C[M=4096,1024] = A[M,1024] * W[1024,1024]^T
// mode: 0 = plain + bias (output proj)
//       1 = Q: head scatter, d-axis sig8 perm, fp32
//       2 = K: head scatter, d-axis sig8 perm, tf32-rounded
//       3 = V: head scatter, seq-row sig8 perm, tf32-rounded
// ---------------------------------------------------------------------------
#define BM 128
#define BN 128
#define BK 32
#define LDT 36
#define TILE_F (BM * LDT)
#define GCHUNKS (EMBED / BK)

__device__ __forceinline__ void load_chunk(const float* __restrict__ A,
                                           const float* __restrict__ W,
                                           int m0, int n0, int c,
                                           uint32_t sa, uint32_t sb, int tid) {
    const float* Ab = A + (size_t)m0 * EMBED + c * BK;
    #pragma unroll
    for (int it = 0; it < 4; it++) {
        int seg = tid + it * 256;
        int r = seg >> 3, s8 = seg & 7;
        cp16(sa + r * (LDT * 4) + s8 * 16, Ab + (size_t)r * EMBED + s8 * 4);
    }
    const float* Wb = W + (size_t)n0 * EMBED + c * BK;
    #pragma unroll
    for (int it = 0; it < 4; it++) {
        int seg = tid + it * 256;
        int r = seg >> 3, s8 = seg & 7;
        cp16(sb + r * (LDT * 4) + s8 * 16, Wb + (size_t)r * EMBED + s8 * 4);
    }
    CP_COMMIT();
}

template <bool RA>
__global__ __launch_bounds__(256, 2) void tc_gemm(
    const float* __restrict__ A, const float* __restrict__ W,
    float* __restrict__ O, const float* __restrict__ bias, int mode)
{
    extern __shared__ __align__(16) float smg[];
    float* As[2] = { smg,            smg + 2 * TILE_F };
    float* Bs[2] = { smg + TILE_F,   smg + 3 * TILE_F };
    const uint32_t sa_u[2] = { smem_to_u32(As[0]), smem_to_u32(As[1]) };
    const uint32_t sb_u[2] = { smem_to_u32(Bs[0]), smem_to_u32(Bs[1]) };

    const int tid = threadIdx.x;
    const int lane = tid & 31;
    const int warp = tid >> 5;
    const int wm = warp >> 1;
    const int wn = warp & 1;
    const int qrow = lane >> 2;
    const int qcol = lane & 3;
    const int m0 = blockIdx.y * BM;
    const int n0 = blockIdx.x * BN;

    float c[2][8][4];
    #pragma unroll
    for (int mt = 0; mt < 2; mt++)
        #pragma unroll
        for (int nt = 0; nt < 8; nt++)
            #pragma unroll
            for (int r = 0; r < 4; r++) c[mt][nt][r] = 0.f;

    load_chunk(A, W, m0, n0, 0, sa_u[0], sb_u[0], tid);
    load_chunk(A, W, m0, n0, 1, sa_u[1], sb_u[1], tid);

    for (int ch = 0; ch < GCHUNKS; ch++) {
        const int buf = ch & 1;
        CP_WAIT1();
        __syncthreads();

        const float* Ab = As[buf] + (wm * 32 + qrow) * LDT + qcol;
        const float* Bb = Bs[buf] + (wn * 64 + qrow) * LDT + qcol;

        #pragma unroll
        for (int kk = 0; kk < BK; kk += 8) {
            uint32_t af[2][4];
            #pragma unroll
            for (int mt = 0; mt < 2; mt++) {
                const float* p = Ab + mt * 16 * LDT + kk;
                float x0 = p[0], x1 = p[8 * LDT], x2 = p[4], x3 = p[8 * LDT + 4];
                if (RA) {
                    af[mt][0] = f2tf32(x0); af[mt][1] = f2tf32(x1);
                    af[mt][2] = f2tf32(x2); af[mt][3] = f2tf32(x3);
                } else {
                    af[mt][0] = __float_as_uint(x0); af[mt][1] = __float_as_uint(x1);
                    af[mt][2] = __float_as_uint(x2); af[mt][3] = __float_as_uint(x3);
                }
            }
            uint32_t bf[8][2];
            #pragma unroll
            for (int nt = 0; nt < 8; nt++) {
                const float* p = Bb + nt * 8 * LDT + kk;
                bf[nt][0] = __float_as_uint(p[0]);
                bf[nt][1] = __float_as_uint(p[4]);
            }
            #pragma unroll
            for (int mt = 0; mt < 2; mt++)
                #pragma unroll
                for (int nt = 0; nt < 8; nt++)
                    mma_tf32_16x8x8(c[mt][nt], af[mt], bf[nt]);
        }

        __syncthreads();
        if (ch + 2 < GCHUNKS)
            load_chunk(A, W, m0, n0, ch + 2, sa_u[buf], sb_u[buf], tid);
    }
    CP_WAIT0();

    #pragma unroll
    for (int mt = 0; mt < 2; mt++) {
        #pragma unroll
        for (int half = 0; half < 2; half++) {
            const int m = m0 + wm * 32 + mt * 16 + half * 8 + qrow;
            #pragma unroll
            for (int nt = 0; nt < 8; nt++) {
                const int n = n0 + wn * 64 + nt * 8 + 2 * qcol;
                float v0 = c[mt][nt][half * 2 + 0];
                float v1 = c[mt][nt][half * 2 + 1];
                if (mode == 0) {
                    float2 bb = *(const float2*)(bias + n);
                    *(float2*)(O + (size_t)m * EMBED + n) =
                        make_float2(v0 + bb.x, v1 + bb.y);
                } else {
                    const int b = m >> 11, s = m & (SEQ - 1);
                    const int h = n >> 6, dd = n & 63;
                    if (mode == 3) {
                        // V: permute seq rows within 8-groups, round to tf32
                        int sp = (s & ~7) | sig8(s & 7);
                        *(uint2*)(O + (((size_t)(b * HEADS + h) * SEQ + sp) * DK + dd)) =
                            make_uint2(f2tf32(v0), f2tf32(v1));
                    } else {
                        // Q/K: permute d cols within 8-groups
                        int dp0 = (dd & ~7) | sig8(dd & 7);
                        int dp1 = ((dd + 1) & ~7) | sig8((dd + 1) & 7);
                        float* base = O + (((size_t)(b * HEADS + h) * SEQ + s) * DK);
                        if (mode == 2) {
                            *(uint32_t*)(base + dp0) = f2tf32(v0);
                            *(uint32_t*)(base + dp1) = f2tf32(v1);
                        } else {
                            base[dp0] = v0;
                            base[dp1] = v1;
                        }
                    }
                }
            }
        }
    }
}

// ---------------------------------------------------------------------------
// Tensor-core flash attention: CTA = 64 Q rows, KV tiles of 64, 128 threads.
// QK^T: Q split hi/lo (2 MMAs), K pre-rounded tf32.  PV: P rounded, V pre-rounded.
// Q/K d-axis and V seq-axis are sig8-permuted by the producer GEMMs.
// ---------------------------------------------------------------------------
#define AP 72   // Q, K, P smem pitch (floats)
#define VP 68   // V smem pitch
#define ATTN_SMEM ((4 * 64 * AP + 2 * 64 * VP) * 4)

__device__ __forceinline__ void load_tile64(uint32_t dst, const float* __restrict__ src,
                                            int pitchf, int tid) {
    #pragma unroll
    for (int it = 0; it < 8; it++) {
        int seg = it * 128 + tid;
        int row = seg >> 4, chk = seg & 15;
        cp16(dst + (uint32_t)(row * pitchf + chk * 4) * 4u, src + row * 64 + chk * 4);
    }
}

__global__ __launch_bounds__(128) void attn_mma()
{
    extern __shared__ __align__(16) float sm[];
    float* Qs  = sm;
    float* Ks0 = sm + 64 * AP;
    float* Ks1 = Ks0 + 64 * AP;
    float* Vs0 = Ks1 + 64 * AP;
    float* Vs1 = Vs0 + 64 * VP;
    float* Ps  = Vs1 + 64 * VP;

    const int qt = (int)gridDim.x - 1 - (int)blockIdx.x;   // longest first
    const int bh = blockIdx.y;
    const int b = bh >> 4, h = bh & 15;
    const int tid = threadIdx.x, lane = tid & 31, w = tid >> 5;
    const int r = lane >> 2, c = lane & 3;

    const float* Qg = g_q + ((size_t)bh * SEQ + qt * 64) * DK;
    const float* Kg = g_k + (size_t)bh * SEQ * DK;
    const float* Vg = g_v + (size_t)bh * SEQ * DK;

    load_tile64(smem_to_u32(Qs), Qg, AP, tid);
    CP_COMMIT();
    load_tile64(smem_to_u32(Ks0), Kg, AP, tid);
    load_tile64(smem_to_u32(Vs0), Vg, VP, tid);
    CP_COMMIT();

    float mr0 = -1e30f, mr1 = -1e30f, lr0 = 0.f, lr1 = 0.f;
    float o[8][4];
    #pragma unroll
    for (int nd = 0; nd < 8; nd++)
        #pragma unroll
        for (int j = 0; j < 4; j++) o[nd][j] = 0.f;

    const int rowg0 = qt * 64 + w * 16 + r;
    const int rowg1 = rowg0 + 8;
    const int sl0 = sig8(2 * c);
    const int sl1 = sig8(2 * c + 1);

    for (int kt = 0; kt <= qt; kt++) {
        const float* Kb = (kt & 1) ? Ks1 : Ks0;
        const float* Vb = (kt & 1) ? Vs1 : Vs0;
        CP_WAIT0();
        __syncthreads();
        if (kt < qt) {
            load_tile64(smem_to_u32((kt & 1) ? Ks0 : Ks1), Kg + (size_t)(kt + 1) * 64 * DK, AP, tid);
            load_tile64(smem_to_u32((kt & 1) ? Vs0 : Vs1), Vg + (size_t)(kt + 1) * 64 * DK, VP, tid);
            CP_COMMIT();
        }

        // ---- S = Q K^T (split-Q: hi+lo) ----
        float s[8][4];
        #pragma unroll
        for (int nt = 0; nt < 8; nt++)
            #pragma unroll
            for (int j = 0; j < 4; j++) s[nt][j] = 0.f;

        const float* Qb = Qs + (w * 16 + r) * AP + 2 * c;
        #pragma unroll
        for (int s8 = 0; s8 < 8; s8++) {
            float2 qa = *(const float2*)(Qb + 8 * s8);
            float2 qb = *(const float2*)(Qb + 8 * s8 + 8 * AP);
            uint32_t ah[4] = { f2tf32(qa.x), f2tf32(qb.x), f2tf32(qa.y), f2tf32(qb.y) };
            uint32_t al[4] = { f2tf32(qa.x - __uint_as_float(ah[0])),
                               f2tf32(qb.x - __uint_as_float(ah[1])),
                               f2tf32(qa.y - __uint_as_float(ah[2])),
                               f2tf32(qb.y - __uint_as_float(ah[3])) };
            #pragma unroll
            for (int nt = 0; nt < 8; nt++) {
                float2 kk = *(const float2*)(Kb + (nt * 8 + r) * AP + 8 * s8 + 2 * c);
                uint32_t bb[2] = { __float_as_uint(kk.x), __float_as_uint(kk.y) };
                mma_tf32_16x8x8(s[nt], ah, bb);
                mma_tf32_16x8x8(s[nt], al, bb);
            }
        }

        // ---- scale, mask, online softmax ----
        const bool diag = (kt == qt);
        float mx0 = -1e30f, mx1 = -1e30f;
        #pragma unroll
        for (int nt = 0; nt < 8; nt++) {
            #pragma unroll
            for (int j = 0; j < 4; j++) s[nt][j] *= 0.125f;
            if (diag) {
                int colb = kt * 64 + nt * 8 + 2 * c;
                if (colb     > rowg0) s[nt][0] = -1e30f;
                if (colb + 1 > rowg0) s[nt][1] = -1e30f;
                if (colb     > rowg1) s[nt][2] = -1e30f;
                if (colb + 1 > rowg1) s[nt][3] = -1e30f;
            }
            mx0 = fmaxf(mx0, fmaxf(s[nt][0], s[nt][1]));
            mx1 = fmaxf(mx1, fmaxf(s[nt][2], s[nt][3]));
        }
        mx0 = fmaxf(mx0, __shfl_xor_sync(0xffffffffu, mx0, 1));
        mx0 = fmaxf(mx0, __shfl_xor_sync(0xffffffffu, mx0, 2));
        mx1 = fmaxf(mx1, __shfl_xor_sync(0xffffffffu, mx1, 1));
        mx1 = fmaxf(mx1, __shfl_xor_sync(0xffffffffu, mx1, 2));

        float nm0 = fmaxf(mr0, mx0), nm1 = fmaxf(mr1, mx1);
        float al0 = __expf(mr0 - nm0), al1 = __expf(mr1 - nm1);
        mr0 = nm0; mr1 = nm1;

        float rs0 = 0.f, rs1 = 0.f;
        float* Pw0 = Ps + (w * 16 + r) * AP;
        float* Pw1 = Pw0 + 8 * AP;
        #pragma unroll
        for (int nt = 0; nt < 8; nt++) {
            float p0 = __uint_as_float(f2tf32(__expf(s[nt][0] - nm0)));
            float p1 = __uint_as_float(f2tf32(__expf(s[nt][1] - nm0)));
            float p2 = __uint_as_float(f2tf32(__expf(s[nt][2] - nm1)));
            float p3 = __uint_as_float(f2tf32(__expf(s[nt][3] - nm1)));
            rs0 += p0 + p1; rs1 += p2 + p3;
            Pw0[nt * 8 + sl0] = p0; Pw0[nt * 8 + sl1] = p1;
            Pw1[nt * 8 + sl0] = p2; Pw1[nt * 8 + sl1] = p3;
        }
        rs0 += __shfl_xor_sync(0xffffffffu, rs0, 1);
        rs0 += __shfl_xor_sync(0xffffffffu, rs0, 2);
        rs1 += __shfl_xor_sync(0xffffffffu, rs1, 1);
        rs1 += __shfl_xor_sync(0xffffffffu, rs1, 2);
        lr0 = lr0 * al0 + rs0;
        lr1 = lr1 * al1 + rs1;
        #pragma unroll
        for (int nd = 0; nd < 8; nd++) {
            o[nd][0] *= al0; o[nd][1] *= al0;
            o[nd][2] *= al1; o[nd][3] *= al1;
        }
        __syncwarp();

        // ---- O += P V ----
        const float* Pb = Ps + (w * 16 + r) * AP + 2 * c;
        #pragma unroll
        for (int s8 = 0; s8 < 8; s8++) {
            float2 pa = *(const float2*)(Pb + 8 * s8);
            float2 pb = *(const float2*)(Pb + 8 * s8 + 8 * AP);
            uint32_t af[4] = { __float_as_uint(pa.x), __float_as_uint(pb.x),
                               __float_as_uint(pa.y), __float_as_uint(pb.y) };
            #pragma unroll
            for (int nd = 0; nd < 8; nd++) {
                float v0 = Vb[(8 * s8 + 2 * c)     * VP + nd * 8 + r];
                float v1 = Vb[(8 * s8 + 2 * c + 1) * VP + nd * 8 + r];
                uint32_t bb[2] = { __float_as_uint(v0), __float_as_uint(v1) };
                mma_tf32_16x8x8(o[nd], af, bb);
            }
        }
    }

    // ---- normalize, round to tf32, write [B,S,E] ----
    float inv0 = 1.f / lr0, inv1 = 1.f / lr1;
    float* O0 = g_att + ((size_t)(b * SEQ + rowg0)) * EMBED + h * 64;
    float* O1 = g_att + ((size_t)(b * SEQ + rowg1)) * EMBED + h * 64;
    #pragma unroll
    for (int nd = 0; nd < 8; nd++) {
        int d0 = nd * 8 + 2 * c;
        *(uint2*)(O0 + d0) = make_uint2(f2tf32(o[nd][0] * inv0), f2tf32(o[nd][1] * inv0));
        *(uint2*)(O1 + d0) = make_uint2(f2tf32(o[nd][2] * inv1), f2tf32(o[nd][3] * inv1));
    }
}

// ---------------------------------------------------------------------------
extern "C" void kernel_launch(void* const* d_in, const int* in_sizes, int n_in,
                              void* d_out, int out_size)
{
    const float* key_   = (const float*)d_in[0];
    const float* query_ = (const float*)d_in[1];
    const float* value_ = (const float*)d_in[2];
    const float* Wq = (const float*)d_in[3];
    const float* Wk = (const float*)d_in[4];
    const float* Wv = (const float*)d_in[5];
    const float* Wo = (const float*)d_in[6];
    const float* bo = (const float*)d_in[7];
    float* out = (float*)d_out;

    float *q_p, *k_p, *v_p, *att_p, *wq_p, *wk_p, *wv_p, *wo_p;
    cudaGetSymbolAddress((void**)&q_p,  g_q);
    cudaGetSymbolAddress((void**)&k_p,  g_k);
    cudaGetSymbolAddress((void**)&v_p,  g_v);
    cudaGetSymbolAddress((void**)&att_p, g_att);
    cudaGetSymbolAddress((void**)&wq_p, g_wq);
    cudaGetSymbolAddress((void**)&wk_p, g_wk);
    cudaGetSymbolAddress((void**)&wv_p, g_wv);
    cudaGetSymbolAddress((void**)&wo_p, g_wo);

    cvt_tf32_kernel<<<EMBED * EMBED / 1024, 256>>>(Wq, wq_p);
    cvt_tf32_kernel<<<EMBED * EMBED / 1024, 256>>>(Wk, wk_p);
    cvt_tf32_kernel<<<EMBED * EMBED / 1024, 256>>>(Wv, wv_p);
    cvt_tf32_kernel<<<EMBED * EMBED / 1024, 256>>>(Wo, wo_p);

    const int gemm_smem = 4 * TILE_F * (int)sizeof(float);
    cudaFuncSetAttribute(tc_gemm<true>,  cudaFuncAttributeMaxDynamicSharedMemorySize, gemm_smem);
    cudaFuncSetAttribute(tc_gemm<false>, cudaFuncAttributeMaxDynamicSharedMemorySize, gemm_smem);
    dim3 gg(EMBED / BN, MTOT / BM);

    tc_gemm<true><<<gg, 256, gemm_smem>>>(query_, wq_p, q_p, nullptr, 1);
    tc_gemm<true><<<gg, 256, gemm_smem>>>(key_,   wk_p, k_p, nullptr, 2);
    tc_gemm<true><<<gg, 256, gemm_smem>>>(value_, wv_p, v_p, nullptr, 3);

    cudaFuncSetAttribute(attn_mma, cudaFuncAttributeMaxDynamicSharedMemorySize, ATTN_SMEM);
    attn_mma<<<dim3(SEQ / 64, BATCH * HEADS), 128, ATTN_SMEM>>>();

    tc_gemm<false><<<gg, 256, gemm_smem>>>(att_p, wo_p, out, bo, 0);
}

// round 5
// speedup vs baseline: 3.2079x; 1.1126x over previous
#include <cuda_runtime.h>
#include <cstdint>

#define EMBED 1024
#define HEADS 16
#define DK 64
#define BATCH 2
#define SEQ 2048
#define MTOT (BATCH*SEQ)   // 4096

// ---------------------------------------------------------------------------
// Scratch
// ---------------------------------------------------------------------------
__device__ float g_q[(size_t)BATCH*HEADS*SEQ*DK];
__device__ float g_k[(size_t)BATCH*HEADS*SEQ*DK];
__device__ float g_v[(size_t)BATCH*HEADS*SEQ*DK];
__device__ float g_att[(size_t)MTOT*EMBED];
__device__ float g_wq[(size_t)EMBED*EMBED];
__device__ float g_wk[(size_t)EMBED*EMBED];
__device__ float g_wv[(size_t)EMBED*EMBED];
__device__ float g_wo[(size_t)EMBED*EMBED];

// ---------------------------------------------------------------------------
// Helpers
// ---------------------------------------------------------------------------
__device__ __forceinline__ uint32_t smem_to_u32(const void* p) {
    uint32_t a;
    asm("{ .reg .u64 t; cvta.to.shared.u64 t, %1; cvt.u32.u64 %0, t; }"
        : "=r"(a) : "l"(p));
    return a;
}
__device__ __forceinline__ uint32_t f2tf32(float x) {
    uint32_t u;
    asm("cvt.rna.tf32.f32 %0, %1;" : "=r"(u) : "f"(x));
    return u;
}
__device__ __forceinline__ void mma_tf32_16x8x8(float c[4], const uint32_t a[4],
                                                const uint32_t b[2]) {
    asm("mma.sync.aligned.m16n8k8.row.col.f32.tf32.tf32.f32 "
        "{%0,%1,%2,%3}, {%4,%5,%6,%7}, {%8,%9}, {%0,%1,%2,%3};"
        : "+f"(c[0]), "+f"(c[1]), "+f"(c[2]), "+f"(c[3])
        : "r"(a[0]), "r"(a[1]), "r"(a[2]), "r"(a[3]), "r"(b[0]), "r"(b[1]));
}
__device__ __forceinline__ void cp16(uint32_t dst, const void* src) {
    asm volatile("cp.async.cg.shared.global [%0], [%1], 16;" :: "r"(dst), "l"(src));
}
#define CP_COMMIT() asm volatile("cp.async.commit_group;" ::: "memory")
#define CP_WAIT1()  asm volatile("cp.async.wait_group 1;" ::: "memory")
#define CP_WAIT0()  asm volatile("cp.async.wait_group 0;" ::: "memory")

// within-8 k-axis permutation: pairs (b, b+4) -> adjacent slots (Q/K d-axis)
__device__ __host__ __forceinline__ int sig8(int b) { return ((b & 3) << 1) | (b >> 2); }

// ---------------------------------------------------------------------------
// Fused fp32 -> tf32 (rna) pre-pass for all 4 weights
// ---------------------------------------------------------------------------
__global__ void cvt4_kernel(const float* __restrict__ wq, const float* __restrict__ wk,
                            const float* __restrict__ wv, const float* __restrict__ wo) {
    const int sel = blockIdx.y;
    const float* in = (sel == 0) ? wq : (sel == 1) ? wk : (sel == 2) ? wv : wo;
    float* out = (sel == 0) ? g_wq : (sel == 1) ? g_wk : (sel == 2) ? g_wv : g_wo;
    size_t i = ((size_t)blockIdx.x * 256 + threadIdx.x) * 4;
    float4 v = *(const float4*)(in + i);
    *(uint4*)(out + i) = make_uint4(f2tf32(v.x), f2tf32(v.y), f2tf32(v.z), f2tf32(v.w));
}

// ---------------------------------------------------------------------------
// tf32 mma.sync GEMM body: C[M=4096,1024] = A[M,1024] * W[1024,1024]^T
// mode: 0 = plain + bias; 1 = Q (scatter + d-perm, fp32);
//       2 = K (scatter + d-perm, tf32); 3 = V (scatter natural, tf32)
// ---------------------------------------------------------------------------
#define BM 128
#define BN 128
#define BK 32
#define LDT 36
#define TILE_F (BM * LDT)
#define GCHUNKS (EMBED / BK)

__device__ __forceinline__ void load_chunk(const float* __restrict__ A,
                                           const float* __restrict__ W,
                                           int m0, int n0, int c,
                                           uint32_t sa, uint32_t sb, int tid) {
    const float* Ab = A + (size_t)m0 * EMBED + c * BK;
    #pragma unroll
    for (int it = 0; it < 4; it++) {
        int seg = tid + it * 256;
        int r = seg >> 3, s8 = seg & 7;
        cp16(sa + r * (LDT * 4) + s8 * 16, Ab + (size_t)r * EMBED + s8 * 4);
    }
    const float* Wb = W + (size_t)n0 * EMBED + c * BK;
    #pragma unroll
    for (int it = 0; it < 4; it++) {
        int seg = tid + it * 256;
        int r = seg >> 3, s8 = seg & 7;
        cp16(sb + r * (LDT * 4) + s8 * 16, Wb + (size_t)r * EMBED + s8 * 4);
    }
    CP_COMMIT();
}

template <bool RA>
__device__ __forceinline__ void gemm_body(
    const float* __restrict__ A, const float* __restrict__ W,
    float* __restrict__ O, const float* __restrict__ bias, int mode,
    float* smg, int bx, int by)
{
    float* As[2] = { smg,            smg + 2 * TILE_F };
    float* Bs[2] = { smg + TILE_F,   smg + 3 * TILE_F };
    const uint32_t sa_u[2] = { smem_to_u32(As[0]), smem_to_u32(As[1]) };
    const uint32_t sb_u[2] = { smem_to_u32(Bs[0]), smem_to_u32(Bs[1]) };

    const int tid = threadIdx.x;
    const int lane = tid & 31;
    const int warp = tid >> 5;
    const int wm = warp >> 1;
    const int wn = warp & 1;
    const int qrow = lane >> 2;
    const int qcol = lane & 3;
    const int m0 = by * BM;
    const int n0 = bx * BN;

    float c[2][8][4];
    #pragma unroll
    for (int mt = 0; mt < 2; mt++)
        #pragma unroll
        for (int nt = 0; nt < 8; nt++)
            #pragma unroll
            for (int r = 0; r < 4; r++) c[mt][nt][r] = 0.f;

    load_chunk(A, W, m0, n0, 0, sa_u[0], sb_u[0], tid);
    load_chunk(A, W, m0, n0, 1, sa_u[1], sb_u[1], tid);

    for (int ch = 0; ch < GCHUNKS; ch++) {
        const int buf = ch & 1;
        CP_WAIT1();
        __syncthreads();

        const float* Ab = As[buf] + (wm * 32 + qrow) * LDT + qcol;
        const float* Bb = Bs[buf] + (wn * 64 + qrow) * LDT + qcol;

        #pragma unroll
        for (int kk = 0; kk < BK; kk += 8) {
            uint32_t af[2][4];
            #pragma unroll
            for (int mt = 0; mt < 2; mt++) {
                const float* p = Ab + mt * 16 * LDT + kk;
                float x0 = p[0], x1 = p[8 * LDT], x2 = p[4], x3 = p[8 * LDT + 4];
                if (RA) {
                    af[mt][0] = f2tf32(x0); af[mt][1] = f2tf32(x1);
                    af[mt][2] = f2tf32(x2); af[mt][3] = f2tf32(x3);
                } else {
                    af[mt][0] = __float_as_uint(x0); af[mt][1] = __float_as_uint(x1);
                    af[mt][2] = __float_as_uint(x2); af[mt][3] = __float_as_uint(x3);
                }
            }
            uint32_t bf[8][2];
            #pragma unroll
            for (int nt = 0; nt < 8; nt++) {
                const float* p = Bb + nt * 8 * LDT + kk;
                bf[nt][0] = __float_as_uint(p[0]);
                bf[nt][1] = __float_as_uint(p[4]);
            }
            #pragma unroll
            for (int mt = 0; mt < 2; mt++)
                #pragma unroll
                for (int nt = 0; nt < 8; nt++)
                    mma_tf32_16x8x8(c[mt][nt], af[mt], bf[nt]);
        }

        __syncthreads();
        if (ch + 2 < GCHUNKS)
            load_chunk(A, W, m0, n0, ch + 2, sa_u[buf], sb_u[buf], tid);
    }
    CP_WAIT0();

    #pragma unroll
    for (int mt = 0; mt < 2; mt++) {
        #pragma unroll
        for (int half = 0; half < 2; half++) {
            const int m = m0 + wm * 32 + mt * 16 + half * 8 + qrow;
            #pragma unroll
            for (int nt = 0; nt < 8; nt++) {
                const int n = n0 + wn * 64 + nt * 8 + 2 * qcol;
                float v0 = c[mt][nt][half * 2 + 0];
                float v1 = c[mt][nt][half * 2 + 1];
                if (mode == 0) {
                    float2 bb = *(const float2*)(bias + n);
                    *(float2*)(O + (size_t)m * EMBED + n) =
                        make_float2(v0 + bb.x, v1 + bb.y);
                } else {
                    const int b = m >> 11, s = m & (SEQ - 1);
                    const int h = n >> 6, dd = n & 63;
                    float* base = O + (((size_t)(b * HEADS + h) * SEQ + s) * DK);
                    if (mode == 3) {
                        // V: natural layout, round to tf32
                        *(uint2*)(base + dd) = make_uint2(f2tf32(v0), f2tf32(v1));
                    } else {
                        // Q/K: permute d within 8-groups
                        int dp0 = (dd & ~7) | sig8(dd & 7);
                        int dp1 = ((dd + 1) & ~7) | sig8((dd + 1) & 7);
                        if (mode == 2) {
                            *(uint32_t*)(base + dp0) = f2tf32(v0);
                            *(uint32_t*)(base + dp1) = f2tf32(v1);
                        } else {
                            base[dp0] = v0;
                            base[dp1] = v1;
                        }
                    }
                }
            }
        }
    }
}

// Merged QKV projection: blockIdx.z selects {query,key,value}
__global__ __launch_bounds__(256, 2) void qkv_gemm(
    const float* __restrict__ Aq, const float* __restrict__ Ak,
    const float* __restrict__ Av)
{
    extern __shared__ __align__(16) float smg[];
    const int z = blockIdx.z;
    const float* A = (z == 0) ? Aq : (z == 1) ? Ak : Av;
    const float* W = (z == 0) ? g_wq : (z == 1) ? g_wk : g_wv;
    float* O = (z == 0) ? g_q : (z == 1) ? g_k : g_v;
    gemm_body<true>(A, W, O, nullptr, z + 1, smg, blockIdx.x, blockIdx.y);
}

// Output projection (A = g_att, already tf32-rounded)
__global__ __launch_bounds__(256, 2) void out_gemm(const float* __restrict__ bias,
                                                   float* __restrict__ O)
{
    extern __shared__ __align__(16) float smg[];
    gemm_body<false>(g_att, g_wo, O, bias, 0, smg, blockIdx.x, blockIdx.y);
}

// ---------------------------------------------------------------------------
// Tensor-core flash attention: CTA = 64 Q rows, KV tiles of 64, 128 threads.
// P stays in registers (quad-shuffle C-frag -> A-frag); V natural layout.
// ---------------------------------------------------------------------------
#define AP 72   // pitch for Q, K, V tiles (floats)
#define ATTN_SMEM (5 * 64 * AP * 4)

__device__ __forceinline__ void load_tile64(uint32_t dst, const float* __restrict__ src,
                                            int tid) {
    #pragma unroll
    for (int it = 0; it < 8; it++) {
        int seg = it * 128 + tid;
        int row = seg >> 4, chk = seg & 15;
        cp16(dst + (uint32_t)(row * AP + chk * 4) * 4u, src + row * 64 + chk * 4);
    }
}

__global__ __launch_bounds__(128) void attn_mma()
{
    extern __shared__ __align__(16) float sm[];
    float* Qs  = sm;
    float* Ks0 = sm + 64 * AP;
    float* Ks1 = Ks0 + 64 * AP;
    float* Vs0 = Ks1 + 64 * AP;
    float* Vs1 = Vs0 + 64 * AP;

    const int qt = (int)gridDim.x - 1 - (int)blockIdx.x;   // longest first
    const int bh = blockIdx.y;
    const int b = bh >> 4, h = bh & 15;
    const int tid = threadIdx.x, lane = tid & 31, w = tid >> 5;
    const int r = lane >> 2, c = lane & 3;

    const float* Qg = g_q + ((size_t)bh * SEQ + qt * 64) * DK;
    const float* Kg = g_k + (size_t)bh * SEQ * DK;
    const float* Vg = g_v + (size_t)bh * SEQ * DK;

    load_tile64(smem_to_u32(Qs), Qg, tid);
    CP_COMMIT();
    load_tile64(smem_to_u32(Ks0), Kg, tid);
    load_tile64(smem_to_u32(Vs0), Vg, tid);
    CP_COMMIT();

    float mr0 = -1e30f, mr1 = -1e30f, lr0 = 0.f, lr1 = 0.f;
    float o[8][4];
    #pragma unroll
    for (int nd = 0; nd < 8; nd++)
        #pragma unroll
        for (int j = 0; j < 4; j++) o[nd][j] = 0.f;

    const int rowg0 = qt * 64 + w * 16 + r;
    const int rowg1 = rowg0 + 8;
    const int srcA = (lane & ~3) | (c >> 1);
    const int srcB = srcA + 2;
    const bool oddc = (c & 1) != 0;

    for (int kt = 0; kt <= qt; kt++) {
        const float* Kb = (kt & 1) ? Ks1 : Ks0;
        const float* Vb = (kt & 1) ? Vs1 : Vs0;
        CP_WAIT0();
        __syncthreads();
        if (kt < qt) {
            load_tile64(smem_to_u32((kt & 1) ? Ks0 : Ks1), Kg + (size_t)(kt + 1) * 64 * DK, tid);
            load_tile64(smem_to_u32((kt & 1) ? Vs0 : Vs1), Vg + (size_t)(kt + 1) * 64 * DK, tid);
            CP_COMMIT();
        }

        // ---- S = Q K^T (split-Q: hi+lo) ----
        float s[8][4];
        #pragma unroll
        for (int nt = 0; nt < 8; nt++)
            #pragma unroll
            for (int j = 0; j < 4; j++) s[nt][j] = 0.f;

        const float* Qb = Qs + (w * 16 + r) * AP + 2 * c;
        #pragma unroll
        for (int s8 = 0; s8 < 8; s8++) {
            float2 qa = *(const float2*)(Qb + 8 * s8);
            float2 qb = *(const float2*)(Qb + 8 * s8 + 8 * AP);
            uint32_t ah[4] = { f2tf32(qa.x), f2tf32(qb.x), f2tf32(qa.y), f2tf32(qb.y) };
            uint32_t al[4] = { f2tf32(qa.x - __uint_as_float(ah[0])),
                               f2tf32(qb.x - __uint_as_float(ah[1])),
                               f2tf32(qa.y - __uint_as_float(ah[2])),
                               f2tf32(qb.y - __uint_as_float(ah[3])) };
            #pragma unroll
            for (int nt = 0; nt < 8; nt++) {
                float2 kk = *(const float2*)(Kb + (nt * 8 + r) * AP + 8 * s8 + 2 * c);
                uint32_t bb[2] = { __float_as_uint(kk.x), __float_as_uint(kk.y) };
                mma_tf32_16x8x8(s[nt], ah, bb);
                mma_tf32_16x8x8(s[nt], al, bb);
            }
        }

        // ---- scale, mask, online softmax ----
        const bool diag = (kt == qt);
        float mx0 = -1e30f, mx1 = -1e30f;
        #pragma unroll
        for (int nt = 0; nt < 8; nt++) {
            #pragma unroll
            for (int j = 0; j < 4; j++) s[nt][j] *= 0.125f;
            if (diag) {
                int colb = kt * 64 + nt * 8 + 2 * c;
                if (colb     > rowg0) s[nt][0] = -1e30f;
                if (colb + 1 > rowg0) s[nt][1] = -1e30f;
                if (colb     > rowg1) s[nt][2] = -1e30f;
                if (colb + 1 > rowg1) s[nt][3] = -1e30f;
            }
            mx0 = fmaxf(mx0, fmaxf(s[nt][0], s[nt][1]));
            mx1 = fmaxf(mx1, fmaxf(s[nt][2], s[nt][3]));
        }
        mx0 = fmaxf(mx0, __shfl_xor_sync(0xffffffffu, mx0, 1));
        mx0 = fmaxf(mx0, __shfl_xor_sync(0xffffffffu, mx0, 2));
        mx1 = fmaxf(mx1, __shfl_xor_sync(0xffffffffu, mx1, 1));
        mx1 = fmaxf(mx1, __shfl_xor_sync(0xffffffffu, mx1, 2));

        float nm0 = fmaxf(mr0, mx0), nm1 = fmaxf(mr1, mx1);
        float al0 = __expf(mr0 - nm0), al1 = __expf(mr1 - nm1);
        mr0 = nm0; mr1 = nm1;

        // P in C-frag layout, tf32-rounded (pu[nt][j] bits)
        uint32_t pu[8][4];
        float rs0 = 0.f, rs1 = 0.f;
        #pragma unroll
        for (int nt = 0; nt < 8; nt++) {
            pu[nt][0] = f2tf32(__expf(s[nt][0] - nm0));
            pu[nt][1] = f2tf32(__expf(s[nt][1] - nm0));
            pu[nt][2] = f2tf32(__expf(s[nt][2] - nm1));
            pu[nt][3] = f2tf32(__expf(s[nt][3] - nm1));
            rs0 += __uint_as_float(pu[nt][0]) + __uint_as_float(pu[nt][1]);
            rs1 += __uint_as_float(pu[nt][2]) + __uint_as_float(pu[nt][3]);
        }
        rs0 += __shfl_xor_sync(0xffffffffu, rs0, 1);
        rs0 += __shfl_xor_sync(0xffffffffu, rs0, 2);
        rs1 += __shfl_xor_sync(0xffffffffu, rs1, 1);
        rs1 += __shfl_xor_sync(0xffffffffu, rs1, 2);
        lr0 = lr0 * al0 + rs0;
        lr1 = lr1 * al1 + rs1;
        #pragma unroll
        for (int nd = 0; nd < 8; nd++) {
            o[nd][0] *= al0; o[nd][1] *= al0;
            o[nd][2] *= al1; o[nd][3] *= al1;
        }

        // ---- O += P V : C-frag -> A-frag via quad shuffles, V natural ----
        #pragma unroll
        for (int g = 0; g < 8; g++) {
            uint32_t u0 = __shfl_sync(0xffffffffu, pu[g][0], srcA);
            uint32_t u1 = __shfl_sync(0xffffffffu, pu[g][1], srcA);
            uint32_t u2 = __shfl_sync(0xffffffffu, pu[g][2], srcA);
            uint32_t u3 = __shfl_sync(0xffffffffu, pu[g][3], srcA);
            uint32_t w0 = __shfl_sync(0xffffffffu, pu[g][0], srcB);
            uint32_t w1 = __shfl_sync(0xffffffffu, pu[g][1], srcB);
            uint32_t w2 = __shfl_sync(0xffffffffu, pu[g][2], srcB);
            uint32_t w3 = __shfl_sync(0xffffffffu, pu[g][3], srcB);
            uint32_t af[4];
            af[0] = oddc ? u1 : u0;   // P[r][c]
            af[1] = oddc ? u3 : u2;   // P[r+8][c]
            af[2] = oddc ? w1 : w0;   // P[r][c+4]
            af[3] = oddc ? w3 : w2;   // P[r+8][c+4]
            const float* Vrow0 = Vb + (8 * g + c) * AP;
            const float* Vrow1 = Vb + (8 * g + c + 4) * AP;
            #pragma unroll
            for (int nd = 0; nd < 8; nd++) {
                uint32_t bb[2] = { __float_as_uint(Vrow0[nd * 8 + r]),
                                   __float_as_uint(Vrow1[nd * 8 + r]) };
                mma_tf32_16x8x8(o[nd], af, bb);
            }
        }
    }

    // ---- normalize, round to tf32, write [B,S,E] ----
    float inv0 = 1.f / lr0, inv1 = 1.f / lr1;
    float* O0 = g_att + ((size_t)(b * SEQ + rowg0)) * EMBED + h * 64;
    float* O1 = g_att + ((size_t)(b * SEQ + rowg1)) * EMBED + h * 64;
    #pragma unroll
    for (int nd = 0; nd < 8; nd++) {
        int d0 = nd * 8 + 2 * c;
        *(uint2*)(O0 + d0) = make_uint2(f2tf32(o[nd][0] * inv0), f2tf32(o[nd][1] * inv0));
        *(uint2*)(O1 + d0) = make_uint2(f2tf32(o[nd][2] * inv1), f2tf32(o[nd][3] * inv1));
    }
}

// ---------------------------------------------------------------------------
extern "C" void kernel_launch(void* const* d_in, const int* in_sizes, int n_in,
                              void* d_out, int out_size)
{
    const float* key_   = (const float*)d_in[0];
    const float* query_ = (const float*)d_in[1];
    const float* value_ = (const float*)d_in[2];
    const float* Wq = (const float*)d_in[3];
    const float* Wk = (const float*)d_in[4];
    const float* Wv = (const float*)d_in[5];
    const float* Wo = (const float*)d_in[6];
    const float* bo = (const float*)d_in[7];
    float* out = (float*)d_out;

    // Fused weight pre-round
    cvt4_kernel<<<dim3(EMBED * EMBED / 1024, 4), 256>>>(Wq, Wk, Wv, Wo);

    const int gemm_smem = 4 * TILE_F * (int)sizeof(float);
    cudaFuncSetAttribute(qkv_gemm, cudaFuncAttributeMaxDynamicSharedMemorySize, gemm_smem);
    cudaFuncSetAttribute(out_gemm, cudaFuncAttributeMaxDynamicSharedMemorySize, gemm_smem);

    // Merged QKV projection: one launch, grid.z = 3
    qkv_gemm<<<dim3(EMBED / BN, MTOT / BM, 3), 256, gemm_smem>>>(query_, key_, value_);

    cudaFuncSetAttribute(attn_mma, cudaFuncAttributeMaxDynamicSharedMemorySize, ATTN_SMEM);
    attn_mma<<<dim3(SEQ / 64, BATCH * HEADS), 128, ATTN_SMEM>>>();

    out_gemm<<<dim3(EMBED / BN, MTOT / BM), 256, gemm_smem>>>(bo, out);
}

// round 7
// speedup vs baseline: 3.2181x; 1.0031x over previous
#include <cuda_runtime.h>
#include <cstdint>

#define EMBED 1024
#define HEADS 16
#define DK 64
#define BATCH 2
#define SEQ 2048
#define MTOT (BATCH*SEQ)   // 4096

// ---------------------------------------------------------------------------
// Scratch
// ---------------------------------------------------------------------------
__device__ float g_q[(size_t)BATCH*HEADS*SEQ*DK];
__device__ float g_k[(size_t)BATCH*HEADS*SEQ*DK];
__device__ float g_v[(size_t)BATCH*HEADS*DK*SEQ];   // transposed [bh][d][s]
__device__ float g_att[(size_t)MTOT*EMBED];
__device__ float g_wq[(size_t)EMBED*EMBED];
__device__ float g_wk[(size_t)EMBED*EMBED];
__device__ float g_wv[(size_t)EMBED*EMBED];
__device__ float g_wo[(size_t)EMBED*EMBED];
__device__ float g_xq[(size_t)MTOT*EMBED];
__device__ float g_xk[(size_t)MTOT*EMBED];
__device__ float g_xv[(size_t)MTOT*EMBED];

// ---------------------------------------------------------------------------
// Helpers
// ---------------------------------------------------------------------------
__device__ __forceinline__ uint32_t smem_to_u32(const void* p) {
    uint32_t a;
    asm("{ .reg .u64 t; cvta.to.shared.u64 t, %1; cvt.u32.u64 %0, t; }"
        : "=r"(a) : "l"(p));
    return a;
}
__device__ __forceinline__ uint32_t f2tf32(float x) {
    uint32_t u;
    asm("cvt.rna.tf32.f32 %0, %1;" : "=r"(u) : "f"(x));
    return u;
}
__device__ __forceinline__ void mma_tf32_16x8x8(float c[4], const uint32_t a[4],
                                                const uint32_t b[2]) {
    asm("mma.sync.aligned.m16n8k8.row.col.f32.tf32.tf32.f32 "
        "{%0,%1,%2,%3}, {%4,%5,%6,%7}, {%8,%9}, {%0,%1,%2,%3};"
        : "+f"(c[0]), "+f"(c[1]), "+f"(c[2]), "+f"(c[3])
        : "r"(a[0]), "r"(a[1]), "r"(a[2]), "r"(a[3]), "r"(b[0]), "r"(b[1]));
}
__device__ __forceinline__ void cp16(uint32_t dst, const void* src) {
    asm volatile("cp.async.cg.shared.global [%0], [%1], 16;" :: "r"(dst), "l"(src));
}
#define CP_COMMIT() asm volatile("cp.async.commit_group;" ::: "memory")
#define CP_WAIT1()  asm volatile("cp.async.wait_group 1;" ::: "memory")
#define CP_WAIT0()  asm volatile("cp.async.wait_group 0;" ::: "memory")

// within-8 permutation: original index b -> slot; pairs (b, b+4) land at (2b, 2b+1)
__device__ __host__ __forceinline__ int sig8(int b) { return ((b & 3) << 1) | (b >> 2); }

// ---------------------------------------------------------------------------
// Pre-passes: fp32 -> tf32 (rna) + sig8 k-axis permutation
// ---------------------------------------------------------------------------
__global__ void cvt4_kernel(const float* __restrict__ wq, const float* __restrict__ wk,
                            const float* __restrict__ wv, const float* __restrict__ wo) {
    const int sel = blockIdx.y;
    const float* in = (sel == 0) ? wq : (sel == 1) ? wk : (sel == 2) ? wv : wo;
    float* out = (sel == 0) ? g_wq : (sel == 1) ? g_wk : (sel == 2) ? g_wv : g_wo;
    size_t i = ((size_t)blockIdx.x * 256 + threadIdx.x) * 4;
    float4 v = *(const float4*)(in + i);
    size_t base = i & ~7ULL;
    int off = (int)(i & 7);
    *(uint32_t*)(out + base + sig8(off + 0)) = f2tf32(v.x);
    *(uint32_t*)(out + base + sig8(off + 1)) = f2tf32(v.y);
    *(uint32_t*)(out + base + sig8(off + 2)) = f2tf32(v.z);
    *(uint32_t*)(out + base + sig8(off + 3)) = f2tf32(v.w);
}

__global__ void prep_act_kernel(const float* __restrict__ q, const float* __restrict__ k,
                                const float* __restrict__ v) {
    const int sel = blockIdx.y;
    const float* in = (sel == 0) ? q : (sel == 1) ? k : v;
    float* out = (sel == 0) ? g_xq : (sel == 1) ? g_xk : g_xv;
    size_t i = ((size_t)blockIdx.x * 256 + threadIdx.x) * 4;
    float4 val = *(const float4*)(in + i);
    size_t base = i & ~7ULL;
    int off = (int)(i & 7);
    *(uint32_t*)(out + base + sig8(off + 0)) = f2tf32(val.x);
    *(uint32_t*)(out + base + sig8(off + 1)) = f2tf32(val.y);
    *(uint32_t*)(out + base + sig8(off + 2)) = f2tf32(val.z);
    *(uint32_t*)(out + base + sig8(off + 3)) = f2tf32(val.w);
}

// ---------------------------------------------------------------------------
// tf32 mma.sync GEMM body. A and W pre-rounded + k-permuted -> LDS.64 frags.
// mode: 0 = plain + bias; 1 = Q (head scatter + d-perm, fp32);
//       2 = K (head scatter + d-perm, tf32); 3 = V (transposed [bh][d][s], s-perm, tf32)
// ---------------------------------------------------------------------------
#define BM 128
#define BN 128
#define BK 32
#define LDT 40
#define TILE_F (BM * LDT)
#define GCHUNKS (EMBED / BK)

__device__ __forceinline__ void load_chunk(const float* __restrict__ A,
                                           const float* __restrict__ W,
                                           int m0, int n0, int c,
                                           uint32_t sa, uint32_t sb, int tid) {
    const float* Ab = A + (size_t)m0 * EMBED + c * BK;
    #pragma unroll
    for (int it = 0; it < 4; it++) {
        int seg = tid + it * 256;
        int r = seg >> 3, s8 = seg & 7;
        cp16(sa + r * (LDT * 4) + s8 * 16, Ab + (size_t)r * EMBED + s8 * 4);
    }
    const float* Wb = W + (size_t)n0 * EMBED + c * BK;
    #pragma unroll
    for (int it = 0; it < 4; it++) {
        int seg = tid + it * 256;
        int r = seg >> 3, s8 = seg & 7;
        cp16(sb + r * (LDT * 4) + s8 * 16, Wb + (size_t)r * EMBED + s8 * 4);
    }
    CP_COMMIT();
}

__device__ __forceinline__ void gemm_body(
    const float* __restrict__ A, const float* __restrict__ W,
    float* __restrict__ O, const float* __restrict__ bias, int mode,
    float* smg, int bx, int by)
{
    float* As[2] = { smg,            smg + 2 * TILE_F };
    float* Bs[2] = { smg + TILE_F,   smg + 3 * TILE_F };
    const uint32_t sa_u[2] = { smem_to_u32(As[0]), smem_to_u32(As[1]) };
    const uint32_t sb_u[2] = { smem_to_u32(Bs[0]), smem_to_u32(Bs[1]) };

    const int tid = threadIdx.x;
    const int lane = tid & 31;
    const int warp = tid >> 5;
    const int wm = warp >> 1;
    const int wn = warp & 1;
    const int qrow = lane >> 2;
    const int qcol = lane & 3;
    const int m0 = by * BM;
    const int n0 = bx * BN;

    float c[2][8][4];
    #pragma unroll
    for (int mt = 0; mt < 2; mt++)
        #pragma unroll
        for (int nt = 0; nt < 8; nt++)
            #pragma unroll
            for (int r = 0; r < 4; r++) c[mt][nt][r] = 0.f;

    load_chunk(A, W, m0, n0, 0, sa_u[0], sb_u[0], tid);
    load_chunk(A, W, m0, n0, 1, sa_u[1], sb_u[1], tid);

    for (int ch = 0; ch < GCHUNKS; ch++) {
        const int buf = ch & 1;
        CP_WAIT1();
        __syncthreads();

        const float* Ab = As[buf] + (wm * 32 + qrow) * LDT + 2 * qcol;
        const float* Bb = Bs[buf] + (wn * 64 + qrow) * LDT + 2 * qcol;

        #pragma unroll
        for (int kk = 0; kk < BK; kk += 8) {
            uint32_t af[2][4];
            #pragma unroll
            for (int mt = 0; mt < 2; mt++) {
                const float* p = Ab + mt * 16 * LDT + kk;
                float2 xa = *(const float2*)p;
                float2 xb = *(const float2*)(p + 8 * LDT);
                af[mt][0] = __float_as_uint(xa.x);
                af[mt][1] = __float_as_uint(xb.x);
                af[mt][2] = __float_as_uint(xa.y);
                af[mt][3] = __float_as_uint(xb.y);
            }
            uint32_t bf[8][2];
            #pragma unroll
            for (int nt = 0; nt < 8; nt++) {
                float2 y = *(const float2*)(Bb + nt * 8 * LDT + kk);
                bf[nt][0] = __float_as_uint(y.x);
                bf[nt][1] = __float_as_uint(y.y);
            }
            #pragma unroll
            for (int mt = 0; mt < 2; mt++)
                #pragma unroll
                for (int nt = 0; nt < 8; nt++)
                    mma_tf32_16x8x8(c[mt][nt], af[mt], bf[nt]);
        }

        __syncthreads();
        if (ch + 2 < GCHUNKS)
            load_chunk(A, W, m0, n0, ch + 2, sa_u[buf], sb_u[buf], tid);
    }
    CP_WAIT0();

    #pragma unroll
    for (int mt = 0; mt < 2; mt++) {
        #pragma unroll
        for (int half = 0; half < 2; half++) {
            const int m = m0 + wm * 32 + mt * 16 + half * 8 + qrow;
            #pragma unroll
            for (int nt = 0; nt < 8; nt++) {
                const int n = n0 + wn * 64 + nt * 8 + 2 * qcol;
                float v0 = c[mt][nt][half * 2 + 0];
                float v1 = c[mt][nt][half * 2 + 1];
                if (mode == 0) {
                    float2 bb = *(const float2*)(bias + n);
                    *(float2*)(O + (size_t)m * EMBED + n) =
                        make_float2(v0 + bb.x, v1 + bb.y);
                } else {
                    const int b = m >> 11, s = m & (SEQ - 1);
                    const int h = n >> 6, dd = n & 63;
                    if (mode == 3) {
                        // V: transposed [bh][d][s], seq sig8-permuted, tf32
                        int sp = (s & ~7) | sig8(s & 7);
                        float* baseT = O + (((size_t)(b * HEADS + h) * DK + dd) * SEQ + sp);
                        *(uint32_t*)baseT = f2tf32(v0);
                        *(uint32_t*)(baseT + SEQ) = f2tf32(v1);
                    } else {
                        // Q/K: [bh][s][d], d-perm within 8-groups
                        int dp0 = (dd & ~7) | sig8(dd & 7);
                        int dp1 = ((dd + 1) & ~7) | sig8((dd + 1) & 7);
                        float* base = O + (((size_t)(b * HEADS + h) * SEQ + s) * DK);
                        if (mode == 2) {
                            *(uint32_t*)(base + dp0) = f2tf32(v0);
                            *(uint32_t*)(base + dp1) = f2tf32(v1);
                        } else {
                            base[dp0] = v0;
                            base[dp1] = v1;
                        }
                    }
                }
            }
        }
    }
}

__global__ __launch_bounds__(256, 2) void qkv_gemm()
{
    extern __shared__ __align__(16) float smg[];
    const int z = blockIdx.z;
    const float* A = (z == 0) ? g_xq : (z == 1) ? g_xk : g_xv;
    const float* W = (z == 0) ? g_wq : (z == 1) ? g_wk : g_wv;
    float* O = (z == 0) ? g_q : (z == 1) ? g_k : g_v;
    gemm_body(A, W, O, nullptr, z + 1, smg, blockIdx.x, blockIdx.y);
}

__global__ __launch_bounds__(256, 2) void out_gemm(const float* __restrict__ bias,
                                                   float* __restrict__ O)
{
    extern __shared__ __align__(16) float smg[];
    gemm_body(g_att, g_wo, O, bias, 0, smg, blockIdx.x, blockIdx.y);
}

// ---------------------------------------------------------------------------
// Tensor-core flash attention: CTA = 64 Q rows, KV tiles of 64, 128 threads.
// Tiles are 64 floats wide -> pitch 72 (64 + 8 pad), conflict-free LDS.64.
// ---------------------------------------------------------------------------
#define AP 72
#define ATTN_SMEM (5 * 64 * AP * 4)   // 92160

__device__ __forceinline__ void load_qk(uint32_t dst, const float* __restrict__ src,
                                        int tid) {
    #pragma unroll
    for (int it = 0; it < 8; it++) {
        int seg = it * 128 + tid;
        int row = seg >> 4, chk = seg & 15;
        cp16(dst + (uint32_t)(row * AP + chk * 4) * 4u, src + row * 64 + chk * 4);
    }
}
__device__ __forceinline__ void load_vt(uint32_t dst, const float* __restrict__ src,
                                        int tid) {
    // src rows d=0..63, row stride SEQ, 64 floats per row
    #pragma unroll
    for (int it = 0; it < 8; it++) {
        int seg = it * 128 + tid;
        int row = seg >> 4, chk = seg & 15;
        cp16(dst + (uint32_t)(row * AP + chk * 4) * 4u, src + (size_t)row * SEQ + chk * 4);
    }
}

__global__ __launch_bounds__(128) void attn_mma()
{
    extern __shared__ __align__(16) float sm[];
    float* Qs  = sm;
    float* Ks0 = sm + 64 * AP;
    float* Ks1 = Ks0 + 64 * AP;
    float* Vs0 = Ks1 + 64 * AP;
    float* Vs1 = Vs0 + 64 * AP;

    const int qt = (int)gridDim.x - 1 - (int)blockIdx.x;   // longest first
    const int bh = blockIdx.y;
    const int b = bh >> 4, h = bh & 15;
    const int tid = threadIdx.x, lane = tid & 31, w = tid >> 5;
    const int r = lane >> 2, c = lane & 3;

    const float* Qg = g_q + ((size_t)bh * SEQ + qt * 64) * DK;
    const float* Kg = g_k + (size_t)bh * SEQ * DK;
    const float* Vg = g_v + (size_t)bh * DK * SEQ;      // transposed

    load_qk(smem_to_u32(Qs), Qg, tid);
    CP_COMMIT();
    load_qk(smem_to_u32(Ks0), Kg, tid);
    load_vt(smem_to_u32(Vs0), Vg, tid);
    CP_COMMIT();

    float mr0 = -1e30f, mr1 = -1e30f, lr0 = 0.f, lr1 = 0.f;
    float o[8][4];
    #pragma unroll
    for (int nd = 0; nd < 8; nd++)
        #pragma unroll
        for (int j = 0; j < 4; j++) o[nd][j] = 0.f;

    const int rowg0 = qt * 64 + w * 16 + r;
    const int rowg1 = rowg0 + 8;
    const int srcA = (lane & ~3) | (c >> 1);
    const int srcB = srcA + 2;
    const bool oddc = (c & 1) != 0;

    for (int kt = 0; kt <= qt; kt++) {
        const float* Kb = (kt & 1) ? Ks1 : Ks0;
        const float* Vb = (kt & 1) ? Vs1 : Vs0;
        CP_WAIT0();
        __syncthreads();
        if (kt < qt) {
            load_qk(smem_to_u32((kt & 1) ? Ks0 : Ks1), Kg + (size_t)(kt + 1) * 64 * DK, tid);
            load_vt(smem_to_u32((kt & 1) ? Vs0 : Vs1), Vg + (size_t)(kt + 1) * 64, tid);
            CP_COMMIT();
        }

        // ---- S = Q K^T (split-Q hi+lo) ----
        float s[8][4];
        #pragma unroll
        for (int nt = 0; nt < 8; nt++)
            #pragma unroll
            for (int j = 0; j < 4; j++) s[nt][j] = 0.f;

        const float* Qb = Qs + (w * 16 + r) * AP + 2 * c;
        #pragma unroll
        for (int s8 = 0; s8 < 8; s8++) {
            float2 qa = *(const float2*)(Qb + 8 * s8);
            float2 qb = *(const float2*)(Qb + 8 * s8 + 8 * AP);
            uint32_t ah[4] = { f2tf32(qa.x), f2tf32(qb.x), f2tf32(qa.y), f2tf32(qb.y) };
            uint32_t al[4] = { f2tf32(qa.x - __uint_as_float(ah[0])),
                               f2tf32(qb.x - __uint_as_float(ah[1])),
                               f2tf32(qa.y - __uint_as_float(ah[2])),
                               f2tf32(qb.y - __uint_as_float(ah[3])) };
            #pragma unroll
            for (int nt = 0; nt < 8; nt++) {
                float2 kk = *(const float2*)(Kb + (nt * 8 + r) * AP + 8 * s8 + 2 * c);
                uint32_t bb[2] = { __float_as_uint(kk.x), __float_as_uint(kk.y) };
                mma_tf32_16x8x8(s[nt], ah, bb);
                mma_tf32_16x8x8(s[nt], al, bb);
            }
        }

        // ---- scale, mask, online softmax ----
        const bool diag = (kt == qt);
        float mx0 = -1e30f, mx1 = -1e30f;
        #pragma unroll
        for (int nt = 0; nt < 8; nt++) {
            #pragma unroll
            for (int j = 0; j < 4; j++) s[nt][j] *= 0.125f;
            if (diag) {
                int colb = kt * 64 + nt * 8 + 2 * c;
                if (colb     > rowg0) s[nt][0] = -1e30f;
                if (colb + 1 > rowg0) s[nt][1] = -1e30f;
                if (colb     > rowg1) s[nt][2] = -1e30f;
                if (colb + 1 > rowg1) s[nt][3] = -1e30f;
            }
            mx0 = fmaxf(mx0, fmaxf(s[nt][0], s[nt][1]));
            mx1 = fmaxf(mx1, fmaxf(s[nt][2], s[nt][3]));
        }
        mx0 = fmaxf(mx0, __shfl_xor_sync(0xffffffffu, mx0, 1));
        mx0 = fmaxf(mx0, __shfl_xor_sync(0xffffffffu, mx0, 2));
        mx1 = fmaxf(mx1, __shfl_xor_sync(0xffffffffu, mx1, 1));
        mx1 = fmaxf(mx1, __shfl_xor_sync(0xffffffffu, mx1, 2));

        float nm0 = fmaxf(mr0, mx0), nm1 = fmaxf(mr1, mx1);
        float al0 = __expf(mr0 - nm0), al1 = __expf(mr1 - nm1);
        mr0 = nm0; mr1 = nm1;

        uint32_t pu[8][4];
        float rs0 = 0.f, rs1 = 0.f;
        #pragma unroll
        for (int nt = 0; nt < 8; nt++) {
            pu[nt][0] = f2tf32(__expf(s[nt][0] - nm0));
            pu[nt][1] = f2tf32(__expf(s[nt][1] - nm0));
            pu[nt][2] = f2tf32(__expf(s[nt][2] - nm1));
            pu[nt][3] = f2tf32(__expf(s[nt][3] - nm1));
            rs0 += __uint_as_float(pu[nt][0]) + __uint_as_float(pu[nt][1]);
            rs1 += __uint_as_float(pu[nt][2]) + __uint_as_float(pu[nt][3]);
        }
        rs0 += __shfl_xor_sync(0xffffffffu, rs0, 1);
        rs0 += __shfl_xor_sync(0xffffffffu, rs0, 2);
        rs1 += __shfl_xor_sync(0xffffffffu, rs1, 1);
        rs1 += __shfl_xor_sync(0xffffffffu, rs1, 2);
        lr0 = lr0 * al0 + rs0;
        lr1 = lr1 * al1 + rs1;
        #pragma unroll
        for (int nd = 0; nd < 8; nd++) {
            o[nd][0] *= al0; o[nd][1] *= al0;
            o[nd][2] *= al1; o[nd][3] *= al1;
        }

        // ---- O += P V : C-frag -> A-frag via quad shuffles; V LDS.64 ----
        #pragma unroll
        for (int g = 0; g < 8; g++) {
            uint32_t u0 = __shfl_sync(0xffffffffu, pu[g][0], srcA);
            uint32_t u1 = __shfl_sync(0xffffffffu, pu[g][1], srcA);
            uint32_t u2 = __shfl_sync(0xffffffffu, pu[g][2], srcA);
            uint32_t u3 = __shfl_sync(0xffffffffu, pu[g][3], srcA);
            uint32_t w0 = __shfl_sync(0xffffffffu, pu[g][0], srcB);
            uint32_t w1 = __shfl_sync(0xffffffffu, pu[g][1], srcB);
            uint32_t w2 = __shfl_sync(0xffffffffu, pu[g][2], srcB);
            uint32_t w3 = __shfl_sync(0xffffffffu, pu[g][3], srcB);
            uint32_t af[4];
            af[0] = oddc ? u1 : u0;
            af[1] = oddc ? u3 : u2;
            af[2] = oddc ? w1 : w0;
            af[3] = oddc ? w3 : w2;
            const float* Vr = Vb + r * AP + 8 * g + 2 * c;   // row d = nd*8 + r
            #pragma unroll
            for (int nd = 0; nd < 8; nd++) {
                float2 vv = *(const float2*)(Vr + nd * 8 * AP);
                uint32_t bb[2] = { __float_as_uint(vv.x), __float_as_uint(vv.y) };
                mma_tf32_16x8x8(o[nd], af, bb);
            }
        }
    }

    // ---- normalize, round to tf32, write [B,S,E] with e-perm ----
    float inv0 = 1.f / lr0, inv1 = 1.f / lr1;
    float* O0 = g_att + ((size_t)(b * SEQ + rowg0)) * EMBED + h * 64;
    float* O1 = g_att + ((size_t)(b * SEQ + rowg1)) * EMBED + h * 64;
    const int p0 = sig8(2 * c), p1 = sig8(2 * c + 1);
    #pragma unroll
    for (int nd = 0; nd < 8; nd++) {
        int d8 = nd * 8;
        *(uint32_t*)(O0 + d8 + p0) = f2tf32(o[nd][0] * inv0);
        *(uint32_t*)(O0 + d8 + p1) = f2tf32(o[nd][1] * inv0);
        *(uint32_t*)(O1 + d8 + p0) = f2tf32(o[nd][2] * inv1);
        *(uint32_t*)(O1 + d8 + p1) = f2tf32(o[nd][3] * inv1);
    }
}

// ---------------------------------------------------------------------------
extern "C" void kernel_launch(void* const* d_in, const int* in_sizes, int n_in,
                              void* d_out, int out_size)
{
    const float* key_   = (const float*)d_in[0];
    const float* query_ = (const float*)d_in[1];
    const float* value_ = (const float*)d_in[2];
    const float* Wq = (const float*)d_in[3];
    const float* Wk = (const float*)d_in[4];
    const float* Wv = (const float*)d_in[5];
    const float* Wo = (const float*)d_in[6];
    const float* bo = (const float*)d_in[7];
    float* out = (float*)d_out;

    cvt4_kernel<<<dim3(EMBED * EMBED / 1024, 4), 256>>>(Wq, Wk, Wv, Wo);
    prep_act_kernel<<<dim3(MTOT * EMBED / 1024, 3), 256>>>(query_, key_, value_);

    const int gemm_smem = 4 * TILE_F * (int)sizeof(float);   // 81920
    cudaFuncSetAttribute(qkv_gemm, cudaFuncAttributeMaxDynamicSharedMemorySize, gemm_smem);
    cudaFuncSetAttribute(out_gemm, cudaFuncAttributeMaxDynamicSharedMemorySize, gemm_smem);

    qkv_gemm<<<dim3(EMBED / BN, MTOT / BM, 3), 256, gemm_smem>>>();

    cudaFuncSetAttribute(attn_mma, cudaFuncAttributeMaxDynamicSharedMemorySize, ATTN_SMEM);
    attn_mma<<<dim3(SEQ / 64, BATCH * HEADS), 128, ATTN_SMEM>>>();

    out_gemm<<<dim3(EMBED / BN, MTOT / BM), 256, gemm_smem>>>(bo, out);
}